// round 9
// baseline (speedup 1.0000x reference)
#include <cuda_runtime.h>
#include <cstdint>

// CTC loss forward, overlapped producer/consumer in ONE kernel.
// Grid = 1024 producer CTAs (bid<1024, 256 thr: CTA b computes log2-softmax
// lp values for all 256 rows of batch b into global scratch, then releases
// flag[b]) + 128 consumer CTAs (bid>=1024, 8 warps; warp w runs the 256-step
// alpha DP for batch (bid-1024)*8+w, acquire-spinning on its flag).
// Producers launch first (bid order) -> all resident in wave 1 -> deadlock-free;
// consumers fill freed slots and overlap with remaining producers.
// Consumer loads go through a cp.async smem ring (4 slots x 8 steps, 3 groups
// in flight) so scratch DRAM latency never touches the serial DP chain.
// A reset kernel zeroes flags each replay (graph edge orders it).

#define TN 256
#define CN 128
#define LN 32
#define BN 1024
#define PADV 127
#define NEGF (-1e30f)
#define LOG2E 1.4426950408889634f
#define NLN2 0.6931471805599453f
#define GK 8                 // DP steps per cp.async group
#define NG (TN / GK)         // 32 groups
#define NR 4                 // ring slots

__device__ float g_lpl[(size_t)BN * TN * LN];  // 32 MB scratch: lp at lab[b][l]
__device__ float g_lpb[(size_t)BN * TN];       // 1 MB: lp at blank
__device__ int   g_flag[BN];

__device__ __forceinline__ float ex2(float x) {
    float r; asm("ex2.approx.f32 %0, %1;" : "=f"(r) : "f"(x)); return r;
}
__device__ __forceinline__ float lg2(float x) {
    float r; asm("lg2.approx.f32 %0, %1;" : "=f"(r) : "f"(x)); return r;
}
__device__ __forceinline__ float lae2(float a, float b) {      // log2-add-exp2
    return fmaxf(a, b) + lg2(1.0f + ex2(-fabsf(a - b)));
}
__device__ __forceinline__ void st_release(int* p, int v) {
    asm volatile("st.release.gpu.global.b32 [%0], %1;" :: "l"(p), "r"(v) : "memory");
}
__device__ __forceinline__ int ld_acquire(const int* p) {
    int v; asm volatile("ld.acquire.gpu.global.b32 %0, [%1];" : "=r"(v) : "l"(p) : "memory");
    return v;
}
__device__ __forceinline__ void cp16(uint32_t smem, const float* g) {
    asm volatile("cp.async.cg.shared.global [%0], [%1], 16;" :: "r"(smem), "l"(g) : "memory");
}
__device__ __forceinline__ void cp_commit() {
    asm volatile("cp.async.commit_group;" ::: "memory");
}
__device__ __forceinline__ void cp_wait2() {
    asm volatile("cp.async.wait_group 2;" ::: "memory");
}

__global__ void reset_kernel() { g_flag[threadIdx.x] = 0; }

__global__ __launch_bounds__(256) void ctc_kernel(
    const int* __restrict__ yt, const float* __restrict__ yp,
    float* __restrict__ out)
{
    const unsigned FULL = 0xffffffffu;
    __shared__ __align__(16) float sl[8][NR][GK * LN];  // 32 KB
    __shared__ __align__(16) float sb[8][NR][GK];       // 1 KB

    const int bid = blockIdx.x;
    const int tid = threadIdx.x;
    const int w = tid >> 5;
    const int l = tid & 31;

    if (bid < BN) {
        // ---------------- producer: lp for batch bid -----------------------
        const int b = bid;
        const float* __restrict__ rowf = yp + (size_t)b * TN * CN;
        const float4* __restrict__ row4 = (const float4*)rowf;
        const int lab = __ldg(yt + b * LN + l);

        #pragma unroll
        for (int i0 = 0; i0 < 32; i0 += 4) {
            float4 v[4];
            #pragma unroll
            for (int j = 0; j < 4; ++j)
                v[j] = row4[(w * 32 + i0 + j) * 32 + l];     // MLP=4
            #pragma unroll
            for (int j = 0; j < 4; ++j) {
                const int t = w * 32 + i0 + j;
                const float x0 = v[j].x * LOG2E, x1 = v[j].y * LOG2E,
                            x2 = v[j].z * LOG2E, x3 = v[j].w * LOG2E;
                float s = ex2(x0) + ex2(x1) + ex2(x2) + ex2(x3);
                #pragma unroll
                for (int o = 16; o; o >>= 1) s += __shfl_xor_sync(FULL, s, o);
                const float logZ = lg2(s);
                const float gl = __ldg(rowf + t * CN + lab) * LOG2E; // L1 hit
                g_lpl[((size_t)b * TN + t) * LN + l] = gl - logZ;
                if (l == 0) g_lpb[(size_t)b * TN + t] = x0 - logZ;   // blank
            }
        }
        __threadfence();
        __syncthreads();
        if (tid == 0) st_release(&g_flag[b], 1);
    } else {
        // ---------------- consumer: DP, one batch per warp ------------------
        const int bb = (bid - BN) * 8 + w;
        const int lab = yt[bb * LN + l];
        const int labp = __shfl_up_sync(FULL, lab, 1);
        const bool skip = (l >= 1) && (lab != labp);
        const unsigned msk = __ballot_sync(FULL, lab != PADV);
        const int len = __popc(msk);

        while (ld_acquire(&g_flag[bb]) == 0) __nanosleep(64);

        const uint32_t slb = (uint32_t)__cvta_generic_to_shared(&sl[w][0][0]);
        const uint32_t sbb = (uint32_t)__cvta_generic_to_shared(&sb[w][0][0]);
        const float* __restrict__ lplg = g_lpl + (size_t)bb * TN * LN;
        const float* __restrict__ lpbg = g_lpb + (size_t)bb * TN;

        // issue one group's cp.asyncs (group = 8 steps = 1024B lpl + 32B lpb)
        auto issue = [&](int g) {
            const int slot = g & (NR - 1);
            const float* srcl = lplg + g * (GK * LN);
            cp16(slb + (uint32_t)(slot * GK * LN + l * 4) * 4,        srcl + l * 4);
            cp16(slb + (uint32_t)(slot * GK * LN + (l + 32) * 4) * 4, srcl + (l + 32) * 4);
            if (l < 2) cp16(sbb + (uint32_t)(slot * GK + l * 4) * 4,  lpbg + g * GK + l * 4);
        };
        issue(0); cp_commit();
        issue(1); cp_commit();
        issue(2); cp_commit();

        float a0 = 0.0f, a_odd = NEGF, a_even = NEGF;  // t=0 folds into step

        for (int g = 0; g < NG; ++g) {
            const int slot = g & (NR - 1);
            cp_wait2();
            __syncwarp();
            #pragma unroll
            for (int i = 0; i < GK; ++i) {
                const float lpl_s = sl[w][slot][i * LN + l];
                const float lpb_s = sb[w][slot][i];
                float po = __shfl_up_sync(FULL, a_odd, 1);   // alpha[2l-1]
                float pe = __shfl_up_sync(FULL, a_even, 1);  // alpha[2l]
                po = (l == 0) ? NEGF : po;
                pe = (l == 0) ? a0 : pe;
                const float pos = skip ? po : NEGF;
                const float m = fmaxf(a_odd, fmaxf(pe, pos));
                const float ssum = ex2(a_odd - m) + ex2(pe - m) + ex2(pos - m);
                const float n_odd = lpl_s + m + lg2(ssum);
                const float n_even = lpb_s + lae2(a_even, a_odd);
                a0 += lpb_s;
                a_odd = n_odd; a_even = n_even;
            }
            __syncwarp();
            if (g + 3 < NG) issue(g + 3);
            cp_commit();
        }

        // loglik ends at states 2*len (even, lane len-1) and 2*len-1 (odd)
        const float ve = __shfl_sync(FULL, a_even, (len - 1) & 31);
        const float vo = __shfl_sync(FULL, a_odd, (len - 1) & 31);
        if (l == 0) {
            const float ll2 = (len >= 1) ? lae2(ve, vo) : a0;
            out[bb] = -ll2 * NLN2;
        }
    }
}

extern "C" void kernel_launch(void* const* d_in, const int* in_sizes, int n_in,
                              void* d_out, int out_size) {
    const int* y_true = (const int*)d_in[0];     // [1024, 32] int32
    const float* y_pred = (const float*)d_in[1]; // [1024, 256, 128] float32
    float* out = (float*)d_out;                  // [1024] float32
    reset_kernel<<<1, BN>>>();
    ctc_kernel<<<BN + BN / 8, 256>>>(y_true, y_pred, out);
}

// round 11
// speedup vs baseline: 1.4272x; 1.4272x over previous
#include <cuda_runtime.h>

// CTC loss forward, fused single-warp, LINEAR-domain alpha DP with per-lane
// power-of-2 rescaling every 4 steps. One warp per batch element (grid=1024).
// Lane l owns extended states 2l+1 (label lab[l]) and 2l+2 (blank); state 0
// (all-blank path) is tracked as a lane-0-local running product.
// Softmax normalization is NOT applied per step: the DP runs on raw exp2
// values; sum(log2 Z_t) is accumulated via a multiplicatively-rescaled
// product and subtracted once at the end. Underflow-to-0 == log-space -inf.
// Per-step serial chain: shfl -> mul(c) -> add -> add -> mul(p). No MUFU on
// the chain.

#define TN 256
#define CN 128
#define LN 32
#define PADV 127
#define LOG2E 1.4426950408889634f
#define NLN2 0.6931471805599453f

__device__ __forceinline__ float ex2(float x) {
    float r; asm("ex2.approx.f32 %0, %1;" : "=f"(r) : "f"(x)); return r;
}
__device__ __forceinline__ float lg2(float x) {
    float r; asm("lg2.approx.f32 %0, %1;" : "=f"(r) : "f"(x)); return r;
}
__device__ __forceinline__ float lae2(float a, float b) {      // log2-add-exp2
    return fmaxf(a, b) + lg2(1.0f + ex2(-fabsf(a - b)));
}

__global__ __launch_bounds__(32) void ctc_lin_kernel(
    const int* __restrict__ yt, const float* __restrict__ yp,
    float* __restrict__ out)
{
    const unsigned FULL = 0xffffffffu;
    const int b = blockIdx.x;
    const int l = threadIdx.x;
    const float* __restrict__ rowf = yp + (size_t)b * TN * CN;
    const float4* __restrict__ row4 = (const float4*)rowf;

    const int lab = yt[b * LN + l];
    const int labp = __shfl_up_sync(FULL, lab, 1);
    const float skipf = (l >= 1 && lab != labp) ? 1.0f : 0.0f;
    const unsigned msk = __ballot_sync(FULL, lab != PADV);
    const int len = __popc(msk);

    float4 rg[4];
    #pragma unroll
    for (int i = 0; i < 4; ++i) rg[i] = row4[i * 32 + l];

    float a_odd = 0.0f, a_even = 0.0f;  // linear, lane-local scale 2^off
    float off = 0.0f;                   // lane log2 scale
    float c = 1.0f;                     // 2^(off[l-1]-off[l]) for this group
    float a0lin = 1.0f;                 // state 0, lane-0's frame (others junk)
    float prodS = 1.0f, cumE = 0.0f;    // running prod of Z_t, rescaled

    #pragma unroll 4
    for (int t = 0; t < TN; ++t) {
        const float4 v = rg[t & 3];
        const int tl = (t + 4 < TN) ? (t + 4) : (TN - 1);
        rg[t & 3] = row4[tl * 32 + l];

        // raw exp2 of logits (no normalization)
        const float x0 = v.x * LOG2E, x1 = v.y * LOG2E,
                    x2 = v.z * LOG2E, x3 = v.w * LOG2E;
        const float ex0 = ex2(x0);
        float s = ex0 + ex2(x1) + ex2(x2) + ex2(x3);
        #pragma unroll
        for (int o = 16; o; o >>= 1) s += __shfl_xor_sync(FULL, s, o);
        prodS *= s;                                       // Z_t (raw)

        const float pb = __shfl_sync(FULL, ex0, 0);       // raw p(blank)
        const float pl = ex2(__ldg(rowf + t * CN + lab) * LOG2E); // raw p(lab[l])

        // state-0 path (pre-update value feeds lane 0's pe)
        const float e0 = a0lin;
        a0lin *= pb;

        // ---- DP chain (short) ----
        float po = __shfl_up_sync(FULL, a_odd, 1);        // alpha[2l-1]
        float pe = __shfl_up_sync(FULL, a_even, 1);       // alpha[2l]
        pe = (l == 0) ? e0 : pe * c;
        const float pos = po * c * skipf;                 // l==0 -> skipf=0
        const float n_odd  = pl * (a_odd + pe + pos);
        const float n_even = pb * (a_even + a_odd);
        a_odd = n_odd; a_even = n_even;

        if ((t & 3) == 3) {
            // per-lane power-of-2 rescale (ALU only, off the chain)
            const float m = fmaxf(a_odd, a_even);
            int eb = (__float_as_int(m) >> 23) & 255;
            int k = (eb == 0) ? 0 : (eb - 127);
            k = (k > 120) ? 120 : k;
            const float sc = __int_as_float((127 - k) << 23);  // 2^-k
            a_odd *= sc; a_even *= sc; a0lin *= sc;
            off += (float)k;
            const float doff = __shfl_up_sync(FULL, off, 1) - off;
            c = ex2(doff);                                 // lane 0's unused
            // rescale Z product
            int ebS = (__float_as_int(prodS) >> 23) & 255;
            int kS = (ebS == 0) ? 0 : (ebS - 127);
            prodS *= __int_as_float((127 - kS) << 23);
            cumE += (float)kS;
        }
    }

    // back to log2 domain in the global (raw) frame
    const float lo = lg2(fmaxf(a_odd, 1e-45f)) + off;
    const float le = lg2(fmaxf(a_even, 1e-45f)) + off;
    const float vo = __shfl_sync(FULL, lo, (len - 1) & 31);  // state 2len-1
    const float ve = __shfl_sync(FULL, le, (len - 1) & 31);  // state 2len
    if (l == 0) {
        const float cumZ = cumE + lg2(prodS);                // sum log2 Z_t
        const float llraw = lae2(ve, vo);
        out[b] = (cumZ - llraw) * NLN2;                      // -loglik (nat)
    }
}

extern "C" void kernel_launch(void* const* d_in, const int* in_sizes, int n_in,
                              void* d_out, int out_size) {
    const int* y_true = (const int*)d_in[0];     // [1024, 32] int32
    const float* y_pred = (const float*)d_in[1]; // [1024, 256, 128] float32
    float* out = (float*)d_out;                  // [1024] float32
    const int B = in_sizes[0] / LN;              // 1024
    ctc_lin_kernel<<<B, 32>>>(y_true, y_pred, out);
}

// round 12
// speedup vs baseline: 1.6053x; 1.1248x over previous
#include <cuda_runtime.h>

// CTC loss forward, midpoint-split: one CTA (2 warps) per batch element.
// Warp 0: forward alpha DP over t=0..127. Warp 1: backward beta DP over
// t=255..128. Combine at m=127: loglik = sum_s alpha_m(s) * beta_m(s).
// Linear-domain DP with per-lane power-of-2 rescaling every 4 steps; raw
// (unnormalized) exp2 probabilities, sum(log2 Z_t) accumulated per half and
// subtracted at the end. Lane l owns extended states 2l+1 (label lab[l]) and
// 2l+2 (blank); state 0 is a lane-0-local running product.

#define TN 256
#define HT 128            // half
#define CN 128
#define LN 32
#define PADV 127
#define LOG2E 1.4426950408889634f
#define NLN2 0.6931471805599453f

__device__ __forceinline__ float ex2(float x) {
    float r; asm("ex2.approx.f32 %0, %1;" : "=f"(r) : "f"(x)); return r;
}
__device__ __forceinline__ float lg2(float x) {
    float r; asm("lg2.approx.f32 %0, %1;" : "=f"(r) : "f"(x)); return r;
}

__global__ __launch_bounds__(64) void ctc_split_kernel(
    const int* __restrict__ yt, const float* __restrict__ yp,
    float* __restrict__ out)
{
    const unsigned FULL = 0xffffffffu;
    __shared__ float s_bo[LN], s_be[LN], s_off[LN];
    __shared__ float s_b0, s_cumZ;

    const int tid = threadIdx.x;
    const int wid = tid >> 5;
    const int l = tid & 31;
    const int b = blockIdx.x;
    const float* __restrict__ rowf = yp + (size_t)b * TN * CN;
    const float4* __restrict__ row4 = (const float4*)rowf;

    const int lab = yt[b * LN + l];
    const unsigned msk = __ballot_sync(FULL, lab != PADV);
    const int len = __popc(msk);

    if (wid == 0) {
        // ---------------- forward alpha, t = 0..127 ------------------------
        const int labp = __shfl_up_sync(FULL, lab, 1);
        const float skipf = (l >= 1 && lab != labp) ? 1.0f : 0.0f;

        float4 rg[4];
        #pragma unroll
        for (int i = 0; i < 4; ++i) rg[i] = row4[i * 32 + l];

        float a_odd = 0.0f, a_even = 0.0f, off = 0.0f, c = 1.0f;
        float a0lin = 1.0f, prodS = 1.0f, cumE = 0.0f;

        #pragma unroll 4
        for (int t = 0; t < HT; ++t) {
            const float4 v = rg[t & 3];
            const int tl = (t + 4 < HT) ? (t + 4) : (HT - 1);
            rg[t & 3] = row4[tl * 32 + l];

            const float x0 = v.x * LOG2E, x1 = v.y * LOG2E,
                        x2 = v.z * LOG2E, x3 = v.w * LOG2E;
            const float ex0 = ex2(x0);
            float s = ex0 + ex2(x1) + ex2(x2) + ex2(x3);
            #pragma unroll
            for (int o = 16; o; o >>= 1) s += __shfl_xor_sync(FULL, s, o);
            prodS *= s;

            const float pb = __shfl_sync(FULL, ex0, 0);
            const float pl = ex2(__ldg(rowf + t * CN + lab) * LOG2E);

            const float e0 = a0lin;
            a0lin *= pb;

            float po = __shfl_up_sync(FULL, a_odd, 1);
            float pe = __shfl_up_sync(FULL, a_even, 1);
            pe = (l == 0) ? e0 : pe * c;
            const float pos = po * c * skipf;
            const float n_odd  = pl * (a_odd + pe + pos);
            const float n_even = pb * (a_even + a_odd);
            a_odd = n_odd; a_even = n_even;

            if ((t & 3) == 3) {
                const float m = fmaxf(a_odd, a_even);
                int eb = (__float_as_int(m) >> 23) & 255;
                int k = (eb == 0) ? 0 : (eb - 127);
                k = (k > 120) ? 120 : k;
                const float sc = __int_as_float((127 - k) << 23);
                a_odd *= sc; a_even *= sc; a0lin *= sc;
                off += (float)k;
                c = ex2(__shfl_up_sync(FULL, off, 1) - off);
                int ebS = (__float_as_int(prodS) >> 23) & 255;
                int kS = (ebS == 0) ? 0 : (ebS - 127);
                prodS *= __int_as_float((127 - kS) << 23);
                cumE += (float)kS;
            }
        }

        __syncthreads();   // beta results visible in smem

        // combine: loglik_raw = sum_s alpha(s)*beta(s)
        float val = a_odd * s_bo[l] + a_even * s_be[l];
        float e = off + s_off[l];
        if (l == 0) val += a0lin * s_b0;
        float ll = lg2(fmaxf(val, 1e-45f)) + e;
        float mm = ll;
        #pragma unroll
        for (int o = 16; o; o >>= 1) mm = fmaxf(mm, __shfl_xor_sync(FULL, mm, o));
        float se = ex2(ll - mm);
        #pragma unroll
        for (int o = 16; o; o >>= 1) se += __shfl_xor_sync(FULL, se, o);
        if (l == 0) {
            const float llraw = mm + lg2(se);
            const float cumZ = cumE + lg2(prodS) + s_cumZ;
            out[b] = (cumZ - llraw) * NLN2;
        }
    } else {
        // ---------------- backward beta, rows r = 255..128 -----------------
        const int labn = __shfl_down_sync(FULL, lab, 1);
        const float skipD = (l < 31 && lab != labn) ? 1.0f : 0.0f;

        float4 rg[4];
        #pragma unroll
        for (int i = 0; i < 4; ++i) rg[i] = row4[(TN - 1 - i) * 32 + l];

        float b_odd = (l == len - 1) ? 1.0f : 0.0f;
        float b_even = b_odd;
        float b0 = 0.0f, off = 0.0f, cD = 1.0f;
        float prodS = 1.0f, cumE = 0.0f;

        #pragma unroll 4
        for (int k0 = 0; k0 < HT; ++k0) {
            const int r = TN - 1 - k0;          // row whose lp we apply
            const float4 v = rg[k0 & 3];
            const int rl = (r - 4 >= HT) ? (r - 4) : HT;
            rg[k0 & 3] = row4[rl * 32 + l];

            const float x0 = v.x * LOG2E, x1 = v.y * LOG2E,
                        x2 = v.z * LOG2E, x3 = v.w * LOG2E;
            const float ex0 = ex2(x0);
            float s = ex0 + ex2(x1) + ex2(x2) + ex2(x3);
            #pragma unroll
            for (int o = 16; o; o >>= 1) s += __shfl_xor_sync(FULL, s, o);
            prodS *= s;

            const float pb = __shfl_sync(FULL, ex0, 0);
            const float pl = ex2(__ldg(rowf + r * CN + lab) * LOG2E);

            // beta_{r-1}(s) = sum_{s'} lp_r(s') beta_r(s')
            const float g_odd = pl * b_odd;
            const float g_even = pb * b_even;
            float gd = __shfl_down_sync(FULL, g_odd, 1) * cD;
            gd = (l < 31) ? gd : 0.0f;
            b0 = pb * b0 + g_odd;               // valid on lane 0
            const float n_odd  = g_odd + g_even + skipD * gd;
            const float n_even = g_even + gd;
            b_odd = n_odd; b_even = n_even;

            if ((k0 & 3) == 3) {
                const float m = fmaxf(b_odd, fmaxf(b_even, (l == 0) ? b0 : 0.0f));
                int eb = (__float_as_int(m) >> 23) & 255;
                int k = (eb == 0) ? 0 : (eb - 127);
                k = (k > 120) ? 120 : k;
                const float sc = __int_as_float((127 - k) << 23);
                b_odd *= sc; b_even *= sc; b0 *= sc;
                off += (float)k;
                cD = ex2(__shfl_down_sync(FULL, off, 1) - off);
                int ebS = (__float_as_int(prodS) >> 23) & 255;
                int kS = (ebS == 0) ? 0 : (ebS - 127);
                prodS *= __int_as_float((127 - kS) << 23);
                cumE += (float)kS;
            }
        }

        s_bo[l] = b_odd;
        s_be[l] = b_even;
        s_off[l] = off;
        if (l == 0) {
            s_b0 = b0;
            s_cumZ = cumE + lg2(prodS);
        }
        __syncthreads();
    }
}

extern "C" void kernel_launch(void* const* d_in, const int* in_sizes, int n_in,
                              void* d_out, int out_size) {
    const int* y_true = (const int*)d_in[0];     // [1024, 32] int32
    const float* y_pred = (const float*)d_in[1]; // [1024, 256, 128] float32
    float* out = (float*)d_out;                  // [1024] float32
    const int B = in_sizes[0] / LN;              // 1024
    ctc_split_kernel<<<B, 64>>>(y_true, y_pred, out);
}